// round 8
// baseline (speedup 1.0000x reference)
#include <cuda_runtime.h>
#include <cuda_bf16.h>
#include <cstdint>
#include <math.h>

// Problem: B=32,T=256 -> M=8192 rows; E=512, H=512; gates i,f,g,o (f unused since c0=0)
#define MROWS 8192
#define HDIM  512

// GEMM tiling
#define BM 128
#define BN 192           // 8 h-blocks of 8, each x3 gates (8-row interleave)
#define BK 32            // bf16 K per chunk (64 bytes per row)
#define NT 256           // 8 warps: 2 (M) x 4 (N); warp tile 64 x 48
#define NSTAGE 4
#define A_ST_BYTES 8192          // 128 rows * 64B, per hi/lo array
#define B_ST_BYTES 12288         // 192 rows * 64B, per hi/lo array
#define STAGE_BYTES (2*A_ST_BYTES + 2*B_ST_BYTES)   // 40960
#define SMEM_TOTAL (NSTAGE * STAGE_BYTES)            // 163840

// ---------------- scratch (device globals; no allocs allowed) ----------------
__device__ __nv_bfloat16 g_A0h[MROWS*512],  g_A0l[MROWS*512];
__device__ __nv_bfloat16 g_A1h[MROWS*1024], g_A1l[MROWS*1024];
__device__ __nv_bfloat16 g_W0h[2*1536*512],  g_W0l[2*1536*512];
__device__ __nv_bfloat16 g_W1h[2*1536*1024], g_W1l[2*1536*1024];
__device__ float g_Bp0[2*1536], g_Bp1[2*1536];
__device__ float g_h0[MROWS*1024], g_h1[MROWS*1024];

// ---------------- PTX helpers (baseline ISA only: sm_80-era) ----------------
__device__ __forceinline__ uint32_t smem_u32(const void* p) {
    uint32_t a;
    asm("{ .reg .u64 t; cvta.to.shared.u64 t, %1; cvt.u32.u64 %0, t; }" : "=r"(a) : "l"(p));
    return a;
}
#define CP_ASYNC16(dst, src) \
    asm volatile("cp.async.cg.shared.global [%0], [%1], 16;" :: "r"(dst), "l"(src))
#define CP_COMMIT() asm volatile("cp.async.commit_group;")
#define CP_WAIT2()  asm volatile("cp.async.wait_group 2;")

#define LDSM_X4(r, addr) \
    asm volatile("ldmatrix.sync.aligned.m8n8.x4.shared.b16 {%0,%1,%2,%3}, [%4];" \
        : "=r"((r)[0]), "=r"((r)[1]), "=r"((r)[2]), "=r"((r)[3]) : "r"(addr))
#define LDSM_X2(r, addr) \
    asm volatile("ldmatrix.sync.aligned.m8n8.x2.shared.b16 {%0,%1}, [%2];" \
        : "=r"((r)[0]), "=r"((r)[1]) : "r"(addr))

#define MMA16816(d, a, b) \
    asm volatile("mma.sync.aligned.m16n8k16.row.col.f32.bf16.bf16.f32 " \
        "{%0,%1,%2,%3}, {%4,%5,%6,%7}, {%8,%9}, {%0,%1,%2,%3};" \
        : "+f"((d)[0]), "+f"((d)[1]), "+f"((d)[2]), "+f"((d)[3]) \
        : "r"((a)[0]), "r"((a)[1]), "r"((a)[2]), "r"((a)[3]), "r"((b)[0]), "r"((b)[1]))

__device__ __forceinline__ float sig_(float x) { return 1.0f / (1.0f + __expf(-x)); }

// 64B rows, 4x16B chunks; conflict-free swizzle for both cp.async and ldmatrix
__device__ __forceinline__ uint32_t swz64(int row, int chunk) {
    return (uint32_t)(row * 64 + ((chunk ^ ((row >> 1) & 3)) << 4));
}

// ---------------- prep kernels ----------------
// Gather emb rows by token, split fp32 -> bf16 hi + lo.
__global__ void gather_split(const int* __restrict__ x, const float* __restrict__ emb)
{
    int id = blockIdx.x * blockDim.x + threadIdx.x;   // over MROWS*128 float4s
    if (id >= MROWS * 128) return;
    int m  = id >> 7;
    int c4 = id & 127;
    int tok = x[m];
    float4 v = *(reinterpret_cast<const float4*>(emb + (size_t)tok * 512) + c4);
    float vv[4] = {v.x, v.y, v.z, v.w};
    size_t o = (size_t)m * 512 + c4 * 4;
#pragma unroll
    for (int q = 0; q < 4; q++) {
        __nv_bfloat16 hi = __float2bfloat16_rn(vv[q]);
        g_A0h[o + q] = hi;
        g_A0l[o + q] = __float2bfloat16_rn(vv[q] - __bfloat162float(hi));
    }
}

// Pack weights, gate-interleaved at n8 granularity:
//   packed row p = hb*24 + gate*8 + hi, h = hb*8 + hi, gates {i,g,o} <- src rows {0,2,3}
// Split fp32 -> bf16 hi/lo; also pack combined biases with the same p index.
template <int K, int LAYER>
__global__ void pack_w(const float* __restrict__ W,
                       const float* __restrict__ bih, const float* __restrict__ bhh)
{
    __nv_bfloat16* Wh = LAYER ? g_W1h : g_W0h;
    __nv_bfloat16* Wl = LAYER ? g_W1l : g_W0l;
    float*         Bp = LAYER ? g_Bp1 : g_Bp0;

    const int KQ = K / 4;
    int id = blockIdx.x * blockDim.x + threadIdx.x;   // over 2*1536*KQ
    if (id >= 2 * 1536 * KQ) return;
    int dir = id / (1536 * KQ);
    int rem = id - dir * 1536 * KQ;
    int p   = rem / KQ;
    int c4  = rem - p * KQ;
    int hb   = p / 24;
    int w    = p - hb * 24;
    int gate = w >> 3;
    int hi   = w & 7;
    int h    = hb * 8 + hi;
    int gsrc = (gate == 0) ? 0 : (gate + 1);   // i->0, g->2, o->3
    size_t src = ((size_t)dir * 2048 + gsrc * 512 + h) * K + c4 * 4;
    size_t dst = ((size_t)dir * 1536 + p) * K + c4 * 4;
    float4 v = *reinterpret_cast<const float4*>(W + src);
    float vv[4] = {v.x, v.y, v.z, v.w};
#pragma unroll
    for (int q = 0; q < 4; q++) {
        __nv_bfloat16 h16 = __float2bfloat16_rn(vv[q]);
        Wh[dst + q] = h16;
        Wl[dst + q] = __float2bfloat16_rn(vv[q] - __bfloat162float(h16));
    }
    if (c4 == 0) {
        int bi = dir * 2048 + gsrc * 512 + h;
        Bp[dir * 1536 + p] = bih[bi] + bhh[bi];
    }
}

// ---------------- fused split-bf16 GEMM (mma.sync) + LSTM epilogue ----------------
template <int K, int LAYER>
__global__ __launch_bounds__(NT, 1) void gemm_lstm(float* __restrict__ hlast,
                                                   float* __restrict__ clast)
{
    extern __shared__ char smem[];
    const uint32_t sb = smem_u32(smem);

    const int tid = threadIdx.x;
    const int wid = tid >> 5;
    const int lid = tid & 31;
    const int warpM = wid >> 2;          // 0..1
    const int warpN = wid & 3;           // 0..3 (48 packed rows each)

    const int m0 = blockIdx.x * BM;
    const int by = blockIdx.y;           // 8 n-tiles of 192 packed rows
    const int d  = blockIdx.z;

    const __nv_bfloat16* Ah = LAYER ? g_A1h : g_A0h;
    const __nv_bfloat16* Al = LAYER ? g_A1l : g_A0l;
    const __nv_bfloat16* Wh = LAYER ? g_W1h : g_W0h;
    const __nv_bfloat16* Wl = LAYER ? g_W1l : g_W0l;
    const float*         Bp = LAYER ? g_Bp1 : g_Bp0;
    const int nrow0 = d * 1536 + by * BN;

    constexpr int NCH = K / BK;

    float acc[4][6][4];
#pragma unroll
    for (int mf = 0; mf < 4; mf++)
#pragma unroll
        for (int g = 0; g < 6; g++)
#pragma unroll
            for (int q = 0; q < 4; q++) acc[mf][g][q] = 0.0f;

    // Loader: A = 1024 x 16B (hi,lo), B = 1536 x 16B (hi,lo) per stage
    auto issue = [&](int kc, int stage) {
        if (kc >= NCH) return;
        const uint32_t so = sb + stage * STAGE_BYTES;
        const int k0 = kc * BK;
#pragma unroll
        for (int it = 0; it < 4; it++) {
            int idx = tid + it * NT;
            int arr = idx >> 9;
            int rem = idx & 511;
            int row = rem >> 2;
            int c   = rem & 3;
            const __nv_bfloat16* g = (arr ? Al : Ah) + (size_t)(m0 + row) * K + k0 + c * 8;
            CP_ASYNC16(so + arr * A_ST_BYTES + swz64(row, c), g);
        }
#pragma unroll
        for (int it = 0; it < 6; it++) {
            int idx = tid + it * NT;
            int arr = (idx >= 768) ? 1 : 0;
            int rem = idx - arr * 768;
            int row = rem >> 2;
            int c   = rem & 3;
            const __nv_bfloat16* g = (arr ? Wl : Wh) + (size_t)(nrow0 + row) * K + k0 + c * 8;
            CP_ASYNC16(so + 2 * A_ST_BYTES + arr * B_ST_BYTES + swz64(row, c), g);
        }
    };

    issue(0, 0); CP_COMMIT();
    issue(1, 1); CP_COMMIT();
    issue(2, 2); CP_COMMIT();

    // per-lane ldmatrix address components
    const int la_row = (lid & 7) + ((lid >> 3) & 1) * 8;   // A: m within frag
    const int la_ch  = (lid >> 4);                          // A: k-half select
    const int lb_row = (lid & 7) + ((lid >> 4) << 3);       // B x4: n within i/g pair
    const int lb_ch  = ((lid >> 3) & 1);                    // B: k-half select
    const int lo_row = 16 + (lid & 7);                      // B x2 (gate o)

    for (int kc = 0; kc < NCH; kc++) {
        CP_WAIT2();
        __syncthreads();
        issue(kc + 3, (kc + 3) % NSTAGE); CP_COMMIT();

        const uint32_t sA = sb + (kc % NSTAGE) * STAGE_BYTES;
        const uint32_t sB = sA + 2 * A_ST_BYTES;

#pragma unroll
        for (int kg = 0; kg < 2; kg++) {
            uint32_t aH[4][4], aL[4][4], bH[6][2], bL[6][2];
#pragma unroll
            for (int mf = 0; mf < 4; mf++) {
                int row = warpM * 64 + mf * 16 + la_row;
                uint32_t addr = sA + swz64(row, kg * 2 + la_ch);
                LDSM_X4(aH[mf], addr);
                LDSM_X4(aL[mf], addr + A_ST_BYTES);
            }
#pragma unroll
            for (int hb = 0; hb < 2; hb++) {
                const int rbase = warpN * 48 + hb * 24;
                uint32_t addr = sB + swz64(rbase + lb_row, kg * 2 + lb_ch);
                uint32_t t[4];
                LDSM_X4(t, addr);
                bH[hb * 3 + 0][0] = t[0]; bH[hb * 3 + 0][1] = t[1];
                bH[hb * 3 + 1][0] = t[2]; bH[hb * 3 + 1][1] = t[3];
                LDSM_X4(t, addr + B_ST_BYTES);
                bL[hb * 3 + 0][0] = t[0]; bL[hb * 3 + 0][1] = t[1];
                bL[hb * 3 + 1][0] = t[2]; bL[hb * 3 + 1][1] = t[3];
                uint32_t addro = sB + swz64(rbase + lo_row, kg * 2 + lb_ch);
                LDSM_X2(bH[hb * 3 + 2], addro);
                LDSM_X2(bL[hb * 3 + 2], addro + B_ST_BYTES);
            }
#pragma unroll
            for (int mf = 0; mf < 4; mf++)
#pragma unroll
                for (int g = 0; g < 6; g++) MMA16816(acc[mf][g], aH[mf], bH[g]);
#pragma unroll
            for (int mf = 0; mf < 4; mf++)
#pragma unroll
                for (int g = 0; g < 6; g++) MMA16816(acc[mf][g], aH[mf], bL[g]);
#pragma unroll
            for (int mf = 0; mf < 4; mf++)
#pragma unroll
                for (int g = 0; g < 6; g++) MMA16816(acc[mf][g], aL[mf], bH[g]);
        }
    }

    // -------- fused LSTM epilogue (thread-local across gates) --------
    const int r  = lid >> 2;
    const int c0 = (lid & 3) * 2;
    float* ghbuf = LAYER ? g_h1 : g_h0;

#pragma unroll
    for (int hb = 0; hb < 2; hb++) {
        const int hbg = by * 8 + warpN * 2 + hb;    // global h-block of 8
        const int pb  = d * 1536 + hbg * 24;
#pragma unroll
        for (int mf = 0; mf < 4; mf++) {
#pragma unroll
            for (int rr = 0; rr < 2; rr++) {
                const int m = m0 + warpM * 64 + mf * 16 + rr * 8 + r;
#pragma unroll
                for (int cc = 0; cc < 2; cc++) {
                    const int hi = c0 + cc;
                    const int h  = hbg * 8 + hi;
                    const int q  = rr * 2 + cc;
                    float iv = acc[mf][hb * 3 + 0][q] + __ldg(&Bp[pb + hi]);
                    float gv = acc[mf][hb * 3 + 1][q] + __ldg(&Bp[pb + 8 + hi]);
                    float ov = acc[mf][hb * 3 + 2][q] + __ldg(&Bp[pb + 16 + hi]);
                    float cv = sig_(iv) * tanhf(gv);
                    float hv = sig_(ov) * tanhf(cv);
                    size_t o = (size_t)m * 1024 + d * HDIM + h;
                    ghbuf[o] = hv;
                    if (LAYER == 0) {
                        __nv_bfloat16 hh = __float2bfloat16_rn(hv);
                        g_A1h[o] = hh;
                        g_A1l[o] = __float2bfloat16_rn(hv - __bfloat162float(hh));
                    }
                    if (d == 0 && (m & 255) == 255) {
                        hlast[(m >> 8) * HDIM + h] = hv;
                        clast[(m >> 8) * HDIM + h] = cv;
                    }
                }
            }
        }
    }
}

// ---------------- combine: enc[b,t,l,h] = h_fwd + h_bwd ----------------
__global__ void combine_kernel(float* __restrict__ enc)
{
    int idx = blockIdx.x * blockDim.x + threadIdx.x;
    const int total = MROWS * HDIM / 4;
    if (idx >= total) return;
    const int m  = idx / (HDIM / 4);
    const int h4 = idx - m * (HDIM / 4);

    const float4* r0a = reinterpret_cast<const float4*>(g_h0 + (size_t)m * 1024) + h4;
    const float4* r0b = reinterpret_cast<const float4*>(g_h0 + (size_t)m * 1024 + 512) + h4;
    const float4* r1a = reinterpret_cast<const float4*>(g_h1 + (size_t)m * 1024) + h4;
    const float4* r1b = reinterpret_cast<const float4*>(g_h1 + (size_t)m * 1024 + 512) + h4;
    float4 a0 = *r0a, b0 = *r0b, a1 = *r1a, b1 = *r1b;
    float4 v0 = make_float4(a0.x + b0.x, a0.y + b0.y, a0.z + b0.z, a0.w + b0.w);
    float4 v1 = make_float4(a1.x + b1.x, a1.y + b1.y, a1.z + b1.z, a1.w + b1.w);
    *(reinterpret_cast<float4*>(enc + ((size_t)m * 2 + 0) * HDIM) + h4) = v0;
    *(reinterpret_cast<float4*>(enc + ((size_t)m * 2 + 1) * HDIM) + h4) = v1;
}

extern "C" void kernel_launch(void* const* d_in, const int* in_sizes, int n_in,
                              void* d_out, int out_size)
{
    (void)in_sizes; (void)n_in; (void)out_size;
    const int*   x    = (const int*)d_in[0];
    const float* emb  = (const float*)d_in[1];
    const float* W0   = (const float*)d_in[2];
    const float* bih0 = (const float*)d_in[4];
    const float* bhh0 = (const float*)d_in[5];
    const float* W1   = (const float*)d_in[6];
    const float* bih1 = (const float*)d_in[8];
    const float* bhh1 = (const float*)d_in[9];

    float* out   = (float*)d_out;
    float* hlast = out;                      // (2,32,512)
    float* clast = out + 2 * 32 * HDIM;      // (2,32,512)
    float* enc   = out + 4 * 32 * HDIM;      // (32,256,2,512)

    cudaFuncSetAttribute(gemm_lstm<512, 0>,  cudaFuncAttributeMaxDynamicSharedMemorySize, SMEM_TOTAL);
    cudaFuncSetAttribute(gemm_lstm<1024, 1>, cudaFuncAttributeMaxDynamicSharedMemorySize, SMEM_TOTAL);

    gather_split<<<(MROWS * 128 + 255) / 256, 256>>>(x, emb);
    pack_w<512, 0><<<(2 * 1536 * 128 + 255) / 256, 256>>>(W0, bih0, bhh0);
    pack_w<1024, 1><<<(2 * 1536 * 256 + 255) / 256, 256>>>(W1, bih1, bhh1);

    dim3 grid(MROWS / BM, 1536 / BN, 2);
    gemm_lstm<512, 0><<<grid, NT, SMEM_TOTAL>>>(hlast, clast);
    gemm_lstm<1024, 1><<<grid, NT, SMEM_TOTAL>>>(hlast + 32 * HDIM, clast + 32 * HDIM);

    combine_kernel<<<(MROWS * HDIM / 4 + 255) / 256, 256>>>(enc);
}

// round 9
// speedup vs baseline: 1.1013x; 1.1013x over previous
#include <cuda_runtime.h>
#include <cuda_bf16.h>
#include <cstdint>
#include <math.h>

// Problem: B=32,T=256 -> M=8192 rows; E=512, H=512; gates i,f,g,o (f unused since c0=0)
#define MROWS 8192
#define HDIM  512

// GEMM tiling (R3-proven shape: 2 CTAs/SM, warp tile 64x24)
#define BM 128
#define BN 96            // 4 h-blocks of 8, each x3 gates (8-row interleave)
#define BK 32            // bf16 K per chunk (64 bytes per row)
#define NT 256           // 8 warps: 2 (M) x 4 (N)
#define NSTAGE 4
#define A_ST_BYTES 8192          // 128 rows * 64B, per hi/lo
#define B_ST_BYTES 6144          // 96 rows * 64B, per hi/lo
#define STAGE_BYTES (2*A_ST_BYTES + 2*B_ST_BYTES)   // 28672
#define SMEM_TOTAL (NSTAGE * STAGE_BYTES)            // 114688 -> 2 CTAs/SM = 229376B

// ---------------- scratch (device globals; no allocs allowed) ----------------
__device__ __nv_bfloat16 g_A0h[MROWS*512],  g_A0l[MROWS*512];
__device__ __nv_bfloat16 g_A1h[MROWS*1024], g_A1l[MROWS*1024];   // L0 output / L1 input
__device__ __nv_bfloat16 g_W0h[2*1536*512],  g_W0l[2*1536*512];
__device__ __nv_bfloat16 g_W1h[2*1536*1024], g_W1l[2*1536*1024];
__device__ float g_Bp0[2*1536], g_Bp1[2*1536];
__device__ float g_h1[MROWS*1024];

// ---------------- PTX helpers (baseline ISA only: sm_80-era) ----------------
__device__ __forceinline__ uint32_t smem_u32(const void* p) {
    uint32_t a;
    asm("{ .reg .u64 t; cvta.to.shared.u64 t, %1; cvt.u32.u64 %0, t; }" : "=r"(a) : "l"(p));
    return a;
}
#define CP_ASYNC16(dst, src) \
    asm volatile("cp.async.cg.shared.global [%0], [%1], 16;" :: "r"(dst), "l"(src))
#define CP_COMMIT() asm volatile("cp.async.commit_group;")
#define CP_WAIT2()  asm volatile("cp.async.wait_group 2;")

#define LDSM_X4(r, addr) \
    asm volatile("ldmatrix.sync.aligned.m8n8.x4.shared.b16 {%0,%1,%2,%3}, [%4];" \
        : "=r"((r)[0]), "=r"((r)[1]), "=r"((r)[2]), "=r"((r)[3]) : "r"(addr))
#define LDSM_X2(r, addr) \
    asm volatile("ldmatrix.sync.aligned.m8n8.x2.shared.b16 {%0,%1}, [%2];" \
        : "=r"((r)[0]), "=r"((r)[1]) : "r"(addr))

#define MMA16816(d, a, b) \
    asm volatile("mma.sync.aligned.m16n8k16.row.col.f32.bf16.bf16.f32 " \
        "{%0,%1,%2,%3}, {%4,%5,%6,%7}, {%8,%9}, {%0,%1,%2,%3};" \
        : "+f"((d)[0]), "+f"((d)[1]), "+f"((d)[2]), "+f"((d)[3]) \
        : "r"((a)[0]), "r"((a)[1]), "r"((a)[2]), "r"((a)[3]), "r"((b)[0]), "r"((b)[1]))

__device__ __forceinline__ float sig_(float x) { return 1.0f / (1.0f + __expf(-x)); }

// 64B rows, 4x16B chunks; conflict-free swizzle for both cp.async and ldmatrix
__device__ __forceinline__ uint32_t swz64(int row, int chunk) {
    return (uint32_t)(row * 64 + ((chunk ^ ((row >> 1) & 3)) << 4));
}

// ---------------- prep kernels ----------------
// Gather emb rows by token, split fp32 -> bf16 hi + lo.
__global__ void gather_split(const int* __restrict__ x, const float* __restrict__ emb)
{
    int id = blockIdx.x * blockDim.x + threadIdx.x;   // over MROWS*128 float4s
    if (id >= MROWS * 128) return;
    int m  = id >> 7;
    int c4 = id & 127;
    int tok = x[m];
    float4 v = *(reinterpret_cast<const float4*>(emb + (size_t)tok * 512) + c4);
    float vv[4] = {v.x, v.y, v.z, v.w};
    size_t o = (size_t)m * 512 + c4 * 4;
#pragma unroll
    for (int q = 0; q < 4; q++) {
        __nv_bfloat16 hi = __float2bfloat16_rn(vv[q]);
        g_A0h[o + q] = hi;
        g_A0l[o + q] = __float2bfloat16_rn(vv[q] - __bfloat162float(hi));
    }
}

// Pack weights, gate-interleaved at n8 granularity:
//   packed row p = hb*24 + gate*8 + hi, h = hb*8 + hi, gates {i,g,o} <- src rows {0,2,3}
// Split fp32 -> bf16 hi/lo; also pack combined biases with the same p index.
template <int K, int LAYER>
__global__ void pack_w(const float* __restrict__ W,
                       const float* __restrict__ bih, const float* __restrict__ bhh)
{
    __nv_bfloat16* Wh = LAYER ? g_W1h : g_W0h;
    __nv_bfloat16* Wl = LAYER ? g_W1l : g_W0l;
    float*         Bp = LAYER ? g_Bp1 : g_Bp0;

    const int KQ = K / 4;
    int id = blockIdx.x * blockDim.x + threadIdx.x;   // over 2*1536*KQ
    if (id >= 2 * 1536 * KQ) return;
    int dir = id / (1536 * KQ);
    int rem = id - dir * 1536 * KQ;
    int p   = rem / KQ;
    int c4  = rem - p * KQ;
    int hb   = p / 24;
    int w    = p - hb * 24;
    int gate = w >> 3;
    int hi   = w & 7;
    int h    = hb * 8 + hi;
    int gsrc = (gate == 0) ? 0 : (gate + 1);   // i->0, g->2, o->3
    size_t src = ((size_t)dir * 2048 + gsrc * 512 + h) * K + c4 * 4;
    size_t dst = ((size_t)dir * 1536 + p) * K + c4 * 4;
    float4 v = *reinterpret_cast<const float4*>(W + src);
    float vv[4] = {v.x, v.y, v.z, v.w};
#pragma unroll
    for (int q = 0; q < 4; q++) {
        __nv_bfloat16 h16 = __float2bfloat16_rn(vv[q]);
        Wh[dst + q] = h16;
        Wl[dst + q] = __float2bfloat16_rn(vv[q] - __bfloat162float(h16));
    }
    if (c4 == 0) {
        int bi = dir * 2048 + gsrc * 512 + h;
        Bp[dir * 1536 + p] = bih[bi] + bhh[bi];
    }
}

// ---------------- fused split-bf16 GEMM (mma.sync) + LSTM epilogue ----------------
template <int K, int LAYER>
__global__ __launch_bounds__(NT) void gemm_lstm(float* __restrict__ hlast,
                                                float* __restrict__ clast)
{
    extern __shared__ char smem[];
    const uint32_t sb = smem_u32(smem);

    const int tid = threadIdx.x;
    const int wid = tid >> 5;
    const int lid = tid & 31;
    const int warpM = wid >> 2;          // 0..1
    const int warpN = wid & 3;           // 0..3

    const int m0 = blockIdx.x * BM;
    const int by = blockIdx.y;           // 16 n-tiles of 96 packed rows
    const int d  = blockIdx.z;

    const __nv_bfloat16* Ah = LAYER ? g_A1h : g_A0h;
    const __nv_bfloat16* Al = LAYER ? g_A1l : g_A0l;
    const __nv_bfloat16* Wh = LAYER ? g_W1h : g_W0h;
    const __nv_bfloat16* Wl = LAYER ? g_W1l : g_W0l;
    const float*         Bp = LAYER ? g_Bp1 : g_Bp0;
    const int nrow0 = d * 1536 + by * BN;

    constexpr int NCH = K / BK;

    float acc[4][3][4];
#pragma unroll
    for (int mf = 0; mf < 4; mf++)
#pragma unroll
        for (int g = 0; g < 3; g++)
#pragma unroll
            for (int q = 0; q < 4; q++) acc[mf][g][q] = 0.0f;

    // Loader: A = 1024 x 16B (hi,lo), B = 768 x 16B (hi,lo) per stage
    auto issue = [&](int kc, int stage) {
        if (kc >= NCH) return;
        const uint32_t so = sb + stage * STAGE_BYTES;
        const int k0 = kc * BK;
#pragma unroll
        for (int it = 0; it < 4; it++) {
            int idx = tid + it * NT;
            int arr = idx >> 9;
            int rem = idx & 511;
            int row = rem >> 2;
            int c   = rem & 3;
            const __nv_bfloat16* g = (arr ? Al : Ah) + (size_t)(m0 + row) * K + k0 + c * 8;
            CP_ASYNC16(so + arr * A_ST_BYTES + swz64(row, c), g);
        }
#pragma unroll
        for (int it = 0; it < 3; it++) {
            int idx = tid + it * NT;
            int arr = (idx >= 384) ? 1 : 0;
            int rem = idx - arr * 384;
            int row = rem >> 2;
            int c   = rem & 3;
            const __nv_bfloat16* g = (arr ? Wl : Wh) + (size_t)(nrow0 + row) * K + k0 + c * 8;
            CP_ASYNC16(so + 2 * A_ST_BYTES + arr * B_ST_BYTES + swz64(row, c), g);
        }
    };

    issue(0, 0); CP_COMMIT();
    issue(1, 1); CP_COMMIT();
    issue(2, 2); CP_COMMIT();

    // per-lane ldmatrix address components
    const int la_row = (lid & 7) + ((lid >> 3) & 1) * 8;   // A: m within frag
    const int la_ch  = (lid >> 4);                          // A: k-half select
    const int lb_row = (lid & 7) + ((lid >> 4) << 3);       // B x4: n within pair
    const int lb_ch  = ((lid >> 3) & 1);                    // B: k-half select
    const int lo_row = 16 + (lid & 7);                      // B x2 (gate o)

    for (int kc = 0; kc < NCH; kc++) {
        CP_WAIT2();
        __syncthreads();
        issue(kc + 3, (kc + 3) % NSTAGE); CP_COMMIT();

        const uint32_t sA = sb + (kc % NSTAGE) * STAGE_BYTES;
        const uint32_t sB = sA + 2 * A_ST_BYTES;

#pragma unroll
        for (int kg = 0; kg < 2; kg++) {
            uint32_t aH[4][4], aL[4][4], bH[3][2], bL[3][2];
#pragma unroll
            for (int mf = 0; mf < 4; mf++) {
                int row = warpM * 64 + mf * 16 + la_row;
                uint32_t addr = sA + swz64(row, kg * 2 + la_ch);
                LDSM_X4(aH[mf], addr);
                LDSM_X4(aL[mf], addr + A_ST_BYTES);
            }
            {
                int row = warpN * 24 + lb_row;
                uint32_t addr = sB + swz64(row, kg * 2 + lb_ch);
                uint32_t t[4];
                LDSM_X4(t, addr);
                bH[0][0] = t[0]; bH[0][1] = t[1]; bH[1][0] = t[2]; bH[1][1] = t[3];
                LDSM_X4(t, addr + B_ST_BYTES);
                bL[0][0] = t[0]; bL[0][1] = t[1]; bL[1][0] = t[2]; bL[1][1] = t[3];
                int rowo = warpN * 24 + lo_row;
                uint32_t addro = sB + swz64(rowo, kg * 2 + lb_ch);
                LDSM_X2(bH[2], addro);
                LDSM_X2(bL[2], addro + B_ST_BYTES);
            }
#pragma unroll
            for (int mf = 0; mf < 4; mf++)
#pragma unroll
                for (int g = 0; g < 3; g++) MMA16816(acc[mf][g], aH[mf], bH[g]);
#pragma unroll
            for (int mf = 0; mf < 4; mf++)
#pragma unroll
                for (int g = 0; g < 3; g++) MMA16816(acc[mf][g], aH[mf], bL[g]);
#pragma unroll
            for (int mf = 0; mf < 4; mf++)
#pragma unroll
                for (int g = 0; g < 3; g++) MMA16816(acc[mf][g], aL[mf], bH[g]);
        }
    }

    // -------- fused LSTM epilogue (thread-local across gates) --------
    const int r  = lid >> 2;
    const int c0 = (lid & 3) * 2;
    const int hb = by * 4 + warpN;          // h-block of 8
    const int pb = d * 1536 + hb * 24;

#pragma unroll
    for (int mf = 0; mf < 4; mf++) {
#pragma unroll
        for (int rr = 0; rr < 2; rr++) {
            const int m = m0 + warpM * 64 + mf * 16 + rr * 8 + r;
#pragma unroll
            for (int cc = 0; cc < 2; cc++) {
                const int hi = c0 + cc;
                const int h  = hb * 8 + hi;
                const int q  = rr * 2 + cc;
                float iv = acc[mf][0][q] + __ldg(&Bp[pb + hi]);
                float gv = acc[mf][1][q] + __ldg(&Bp[pb + 8 + hi]);
                float ov = acc[mf][2][q] + __ldg(&Bp[pb + 16 + hi]);
                float cv = sig_(iv) * tanhf(gv);
                float hv = sig_(ov) * tanhf(cv);
                size_t o = (size_t)m * 1024 + d * HDIM + h;
                if (LAYER == 0) {
                    // L0 output only as bf16 hi/lo split (L1 input + combine source)
                    __nv_bfloat16 hh = __float2bfloat16_rn(hv);
                    g_A1h[o] = hh;
                    g_A1l[o] = __float2bfloat16_rn(hv - __bfloat162float(hh));
                } else {
                    g_h1[o] = hv;
                }
                if (d == 0 && (m & 255) == 255) {
                    hlast[(m >> 8) * HDIM + h] = hv;
                    clast[(m >> 8) * HDIM + h] = cv;
                }
            }
        }
    }
}

// ---------------- combine: enc[b,t,l,h] = h_l_fwd + h_l_bwd ----------------
// l=0 reconstructed from bf16 hi/lo split (hi+lo, ~4e-6 err); l=1 from fp32.
__global__ void combine_kernel(float* __restrict__ enc)
{
    int idx = blockIdx.x * blockDim.x + threadIdx.x;
    const int total = MROWS * 128;    // 4 h-values per thread
    if (idx >= total) return;
    const int m  = idx >> 7;
    const int h4 = idx & 127;
    const size_t base = (size_t)m * 1024 + h4 * 4;

    // l=0: fwd at +0, bwd at +512
    float v0[4];
    {
        const __nv_bfloat16* hf = g_A1h + base;
        const __nv_bfloat16* lf = g_A1l + base;
        const __nv_bfloat16* hbk = g_A1h + base + 512;
        const __nv_bfloat16* lbk = g_A1l + base + 512;
        uint2 a = *reinterpret_cast<const uint2*>(hf);
        uint2 b = *reinterpret_cast<const uint2*>(lf);
        uint2 c = *reinterpret_cast<const uint2*>(hbk);
        uint2 e = *reinterpret_cast<const uint2*>(lbk);
        const __nv_bfloat16* ap = reinterpret_cast<const __nv_bfloat16*>(&a);
        const __nv_bfloat16* bp = reinterpret_cast<const __nv_bfloat16*>(&b);
        const __nv_bfloat16* cp = reinterpret_cast<const __nv_bfloat16*>(&c);
        const __nv_bfloat16* ep = reinterpret_cast<const __nv_bfloat16*>(&e);
#pragma unroll
        for (int q = 0; q < 4; q++)
            v0[q] = (__bfloat162float(ap[q]) + __bfloat162float(bp[q]))
                  + (__bfloat162float(cp[q]) + __bfloat162float(ep[q]));
    }
    // l=1: fp32
    float4 a1 = *reinterpret_cast<const float4*>(g_h1 + base);
    float4 b1 = *reinterpret_cast<const float4*>(g_h1 + base + 512);
    float4 v1 = make_float4(a1.x + b1.x, a1.y + b1.y, a1.z + b1.z, a1.w + b1.w);

    float4 v0f = make_float4(v0[0], v0[1], v0[2], v0[3]);
    *reinterpret_cast<float4*>(enc + ((size_t)m * 2 + 0) * HDIM + h4 * 4) = v0f;
    *reinterpret_cast<float4*>(enc + ((size_t)m * 2 + 1) * HDIM + h4 * 4) = v1;
}

extern "C" void kernel_launch(void* const* d_in, const int* in_sizes, int n_in,
                              void* d_out, int out_size)
{
    (void)in_sizes; (void)n_in; (void)out_size;
    const int*   x    = (const int*)d_in[0];
    const float* emb  = (const float*)d_in[1];
    const float* W0   = (const float*)d_in[2];
    const float* bih0 = (const float*)d_in[4];
    const float* bhh0 = (const float*)d_in[5];
    const float* W1   = (const float*)d_in[6];
    const float* bih1 = (const float*)d_in[8];
    const float* bhh1 = (const float*)d_in[9];

    float* out   = (float*)d_out;
    float* hlast = out;                      // (2,32,512)
    float* clast = out + 2 * 32 * HDIM;      // (2,32,512)
    float* enc   = out + 4 * 32 * HDIM;      // (32,256,2,512)

    cudaFuncSetAttribute(gemm_lstm<512, 0>,  cudaFuncAttributeMaxDynamicSharedMemorySize, SMEM_TOTAL);
    cudaFuncSetAttribute(gemm_lstm<1024, 1>, cudaFuncAttributeMaxDynamicSharedMemorySize, SMEM_TOTAL);

    gather_split<<<(MROWS * 128 + 255) / 256, 256>>>(x, emb);
    pack_w<512, 0><<<(2 * 1536 * 128 + 255) / 256, 256>>>(W0, bih0, bhh0);
    pack_w<1024, 1><<<(2 * 1536 * 256 + 255) / 256, 256>>>(W1, bih1, bhh1);

    dim3 grid(MROWS / BM, 1536 / BN, 2);
    gemm_lstm<512, 0><<<grid, NT, SMEM_TOTAL>>>(hlast, clast);
    gemm_lstm<1024, 1><<<grid, NT, SMEM_TOTAL>>>(hlast + 32 * HDIM, clast + 32 * HDIM);

    combine_kernel<<<(MROWS * 128 + 255) / 256, 256>>>(enc);
}

// round 10
// speedup vs baseline: 1.2722x; 1.1552x over previous
#include <cuda_runtime.h>
#include <cuda_bf16.h>
#include <cstdint>
#include <math.h>

// Problem: B=32,T=256 -> M=8192 rows; E=512, H=512; gates i,f,g,o (f unused since c0=0)
#define MROWS 8192
#define HDIM  512

// GEMM tiling (2 CTAs/SM, warp tile 64x24, regs capped at 128)
#define BM 128
#define BN 96            // 4 h-blocks of 8, each x3 gates (8-row interleave)
#define BK 32            // bf16 K per chunk (64 bytes per row)
#define NT 256           // 8 warps: 2 (M) x 4 (N)
#define NSTAGE 4
#define A_ST_BYTES 8192          // 128 rows * 64B, per hi/lo
#define B_ST_BYTES 6144          // 96 rows * 64B, per hi/lo
#define STAGE_BYTES (2*A_ST_BYTES + 2*B_ST_BYTES)   // 28672
#define MBAR_OFF    (NSTAGE * STAGE_BYTES)           // 114688
#define SMEM_TOTAL  (MBAR_OFF + 64)                  // 114752 -> 2 CTAs/SM

// ---------------- scratch (device globals; no allocs allowed) ----------------
__device__ __nv_bfloat16 g_A0h[MROWS*512],  g_A0l[MROWS*512];
__device__ __nv_bfloat16 g_A1h[MROWS*1024], g_A1l[MROWS*1024];   // L0 output / L1 input
__device__ __nv_bfloat16 g_W0h[2*1536*512],  g_W0l[2*1536*512];
__device__ __nv_bfloat16 g_W1h[2*1536*1024], g_W1l[2*1536*1024];
__device__ float g_Bp0[2*1536], g_Bp1[2*1536];
__device__ float g_h1[MROWS*1024];

// ---------------- PTX helpers (baseline ISA only) ----------------
__device__ __forceinline__ uint32_t smem_u32(const void* p) {
    uint32_t a;
    asm("{ .reg .u64 t; cvta.to.shared.u64 t, %1; cvt.u32.u64 %0, t; }" : "=r"(a) : "l"(p));
    return a;
}
#define CP_ASYNC16(dst, src) \
    asm volatile("cp.async.cg.shared.global [%0], [%1], 16;" :: "r"(dst), "l"(src))
#define CP_MBAR_ARRIVE(mb) \
    asm volatile("cp.async.mbarrier.arrive.noinc.shared.b64 [%0];" :: "r"(mb) : "memory")
#define MBAR_INIT(mb, c) \
    asm volatile("mbarrier.init.shared.b64 [%0], %1;" :: "r"(mb), "r"(c) : "memory")
#define MBAR_ARRIVE(mb) \
    asm volatile("{ .reg .b64 t; mbarrier.arrive.shared.b64 t, [%0]; }" :: "r"(mb) : "memory")

__device__ __forceinline__ void mbar_wait(uint32_t mb, uint32_t parity) {
    asm volatile(
        "{\n\t.reg .pred P;\n\t"
        "WL_%=:\n\t"
        "mbarrier.try_wait.parity.shared.b64 P, [%0], %1;\n\t"
        "@P bra.uni WD_%=;\n\t"
        "bra.uni WL_%=;\n\t"
        "WD_%=:\n\t}"
        :: "r"(mb), "r"(parity) : "memory");
}

#define LDSM_X4(r, addr) \
    asm volatile("ldmatrix.sync.aligned.m8n8.x4.shared.b16 {%0,%1,%2,%3}, [%4];" \
        : "=r"((r)[0]), "=r"((r)[1]), "=r"((r)[2]), "=r"((r)[3]) : "r"(addr))
#define LDSM_X2(r, addr) \
    asm volatile("ldmatrix.sync.aligned.m8n8.x2.shared.b16 {%0,%1}, [%2];" \
        : "=r"((r)[0]), "=r"((r)[1]) : "r"(addr))

#define MMA16816(d, a, b) \
    asm volatile("mma.sync.aligned.m16n8k16.row.col.f32.bf16.bf16.f32 " \
        "{%0,%1,%2,%3}, {%4,%5,%6,%7}, {%8,%9}, {%0,%1,%2,%3};" \
        : "+f"((d)[0]), "+f"((d)[1]), "+f"((d)[2]), "+f"((d)[3]) \
        : "r"((a)[0]), "r"((a)[1]), "r"((a)[2]), "r"((a)[3]), "r"((b)[0]), "r"((b)[1]))

__device__ __forceinline__ float sig_(float x) { return 1.0f / (1.0f + __expf(-x)); }

// 64B rows, 4x16B chunks; conflict-free swizzle for both cp.async and ldmatrix
__device__ __forceinline__ uint32_t swz64(int row, int chunk) {
    return (uint32_t)(row * 64 + ((chunk ^ ((row >> 1) & 3)) << 4));
}

// ---------------- prep kernels ----------------
__global__ void gather_split(const int* __restrict__ x, const float* __restrict__ emb)
{
    int id = blockIdx.x * blockDim.x + threadIdx.x;   // over MROWS*128 float4s
    if (id >= MROWS * 128) return;
    int m  = id >> 7;
    int c4 = id & 127;
    int tok = x[m];
    float4 v = *(reinterpret_cast<const float4*>(emb + (size_t)tok * 512) + c4);
    float vv[4] = {v.x, v.y, v.z, v.w};
    size_t o = (size_t)m * 512 + c4 * 4;
#pragma unroll
    for (int q = 0; q < 4; q++) {
        __nv_bfloat16 hi = __float2bfloat16_rn(vv[q]);
        g_A0h[o + q] = hi;
        g_A0l[o + q] = __float2bfloat16_rn(vv[q] - __bfloat162float(hi));
    }
}

// packed row p = hb*24 + gate*8 + hi, h = hb*8 + hi, gates {i,g,o} <- src rows {0,2,3}
template <int K, int LAYER>
__global__ void pack_w(const float* __restrict__ W,
                       const float* __restrict__ bih, const float* __restrict__ bhh)
{
    __nv_bfloat16* Wh = LAYER ? g_W1h : g_W0h;
    __nv_bfloat16* Wl = LAYER ? g_W1l : g_W0l;
    float*         Bp = LAYER ? g_Bp1 : g_Bp0;

    const int KQ = K / 4;
    int id = blockIdx.x * blockDim.x + threadIdx.x;   // over 2*1536*KQ
    if (id >= 2 * 1536 * KQ) return;
    int dir = id / (1536 * KQ);
    int rem = id - dir * 1536 * KQ;
    int p   = rem / KQ;
    int c4  = rem - p * KQ;
    int hb   = p / 24;
    int w    = p - hb * 24;
    int gate = w >> 3;
    int hi   = w & 7;
    int h    = hb * 8 + hi;
    int gsrc = (gate == 0) ? 0 : (gate + 1);   // i->0, g->2, o->3
    size_t src = ((size_t)dir * 2048 + gsrc * 512 + h) * K + c4 * 4;
    size_t dst = ((size_t)dir * 1536 + p) * K + c4 * 4;
    float4 v = *reinterpret_cast<const float4*>(W + src);
    float vv[4] = {v.x, v.y, v.z, v.w};
#pragma unroll
    for (int q = 0; q < 4; q++) {
        __nv_bfloat16 h16 = __float2bfloat16_rn(vv[q]);
        Wh[dst + q] = h16;
        Wl[dst + q] = __float2bfloat16_rn(vv[q] - __bfloat162float(h16));
    }
    if (c4 == 0) {
        int bi = dir * 2048 + gsrc * 512 + h;
        Bp[dir * 1536 + p] = bih[bi] + bhh[bi];
    }
}

// ---------------- fused split-bf16 GEMM (mma.sync, mbarrier pipeline) ----------------
template <int K, int LAYER>
__global__ __launch_bounds__(NT, 2) void gemm_lstm(float* __restrict__ hlast,
                                                   float* __restrict__ clast)
{
    extern __shared__ char smem[];
    const uint32_t sb = smem_u32(smem);
    const uint32_t mb_full  = sb + MBAR_OFF;        // 4 x 8B
    const uint32_t mb_empty = sb + MBAR_OFF + 32;   // 4 x 8B

    const int tid = threadIdx.x;
    const int wid = tid >> 5;
    const int lid = tid & 31;
    const int warpM = wid >> 2;          // 0..1
    const int warpN = wid & 3;           // 0..3

    const int m0 = blockIdx.x * BM;
    const int by = blockIdx.y;           // 16 n-tiles of 96 packed rows
    const int d  = blockIdx.z;

    const __nv_bfloat16* Ah = LAYER ? g_A1h : g_A0h;
    const __nv_bfloat16* Al = LAYER ? g_A1l : g_A0l;
    const __nv_bfloat16* Wh = LAYER ? g_W1h : g_W0h;
    const __nv_bfloat16* Wl = LAYER ? g_W1l : g_W0l;
    const float*         Bp = LAYER ? g_Bp1 : g_Bp0;
    const int nrow0 = d * 1536 + by * BN;

    constexpr int NCH = K / BK;

    if (tid == 0) {
#pragma unroll
        for (int s = 0; s < NSTAGE; s++) {
            MBAR_INIT(mb_full  + 8 * s, NT);
            MBAR_INIT(mb_empty + 8 * s, NT);
        }
    }
    __syncthreads();

    // ---- hoisted per-thread loader state ----
    // A: row = tid>>2 (and +64), chunk = tid&3; arrays hi & lo
    const int arow = tid >> 2;
    const int ach  = tid & 3;
    const __nv_bfloat16* aSrcH = Ah + (size_t)(m0 + arow) * K + ach * 8;
    const __nv_bfloat16* aSrcL = Al + (size_t)(m0 + arow) * K + ach * 8;
    const uint32_t aDst = swz64(arow, ach);          // +4096 for row+64
    // B: 3 iterations, array/row/chunk vary per it
    const __nv_bfloat16* bSrc[3];
    uint32_t bDst[3];
#pragma unroll
    for (int it = 0; it < 3; it++) {
        int idx = tid + it * NT;
        int arr = (idx >= 384) ? 1 : 0;
        int rem = idx - arr * 384;
        int row = rem >> 2;
        int c   = rem & 3;
        bSrc[it] = (arr ? Wl : Wh) + (size_t)(nrow0 + row) * K + c * 8;
        bDst[it] = 2 * A_ST_BYTES + arr * B_ST_BYTES + swz64(row, c);
    }

    auto issue = [&](int kc, int stage) {
        const uint32_t so = sb + stage * STAGE_BYTES;
        const int ko = kc * BK;
        CP_ASYNC16(so + aDst,                       aSrcH + ko);
        CP_ASYNC16(so + aDst + 4096,                aSrcH + ko + (size_t)64 * K);
        CP_ASYNC16(so + A_ST_BYTES + aDst,          aSrcL + ko);
        CP_ASYNC16(so + A_ST_BYTES + aDst + 4096,   aSrcL + ko + (size_t)64 * K);
#pragma unroll
        for (int it = 0; it < 3; it++)
            CP_ASYNC16(so + bDst[it], bSrc[it] + ko);
        CP_MBAR_ARRIVE(mb_full + 8 * stage);
    };

    float acc[4][3][4];
#pragma unroll
    for (int mf = 0; mf < 4; mf++)
#pragma unroll
        for (int g = 0; g < 3; g++)
#pragma unroll
            for (int q = 0; q < 4; q++) acc[mf][g][q] = 0.0f;

    // prologue fills (stages 0..2)
    issue(0, 0);
    issue(1, 1);
    issue(2, 2);

    // per-lane ldmatrix address components
    const int la_row = (lid & 7) + ((lid >> 3) & 1) * 8;   // A: m within frag
    const int la_ch  = (lid >> 4);                          // A: k-half select
    const int lb_row = (lid & 7) + ((lid >> 4) << 3);       // B x4: n within pair
    const int lb_ch  = ((lid >> 3) & 1);                    // B: k-half select
    const int lo_row = 16 + (lid & 7);                      // B x2 (gate o)

    for (int kc = 0; kc < NCH; kc++) {
        const int st = kc & 3;
        mbar_wait(mb_full + 8 * st, (kc >> 2) & 1);

        const uint32_t sA = sb + st * STAGE_BYTES;
        const uint32_t sB = sA + 2 * A_ST_BYTES;

#pragma unroll
        for (int kg = 0; kg < 2; kg++) {
            uint32_t aH[4][4], aL[4][4], bH[3][2], bL[3][2];
#pragma unroll
            for (int mf = 0; mf < 4; mf++) {
                int row = warpM * 64 + mf * 16 + la_row;
                uint32_t addr = sA + swz64(row, kg * 2 + la_ch);
                LDSM_X4(aH[mf], addr);
                LDSM_X4(aL[mf], addr + A_ST_BYTES);
            }
            {
                int row = warpN * 24 + lb_row;
                uint32_t addr = sB + swz64(row, kg * 2 + lb_ch);
                uint32_t t[4];
                LDSM_X4(t, addr);
                bH[0][0] = t[0]; bH[0][1] = t[1]; bH[1][0] = t[2]; bH[1][1] = t[3];
                LDSM_X4(t, addr + B_ST_BYTES);
                bL[0][0] = t[0]; bL[0][1] = t[1]; bL[1][0] = t[2]; bL[1][1] = t[3];
                int rowo = warpN * 24 + lo_row;
                uint32_t addro = sB + swz64(rowo, kg * 2 + lb_ch);
                LDSM_X2(bH[2], addro);
                LDSM_X2(bL[2], addro + B_ST_BYTES);
            }
#pragma unroll
            for (int mf = 0; mf < 4; mf++)
#pragma unroll
                for (int g = 0; g < 3; g++) MMA16816(acc[mf][g], aH[mf], bH[g]);
#pragma unroll
            for (int mf = 0; mf < 4; mf++)
#pragma unroll
                for (int g = 0; g < 3; g++) MMA16816(acc[mf][g], aH[mf], bL[g]);
#pragma unroll
            for (int mf = 0; mf < 4; mf++)
#pragma unroll
                for (int g = 0; g < 3; g++) MMA16816(acc[mf][g], aL[mf], bH[g]);
        }

        // done reading stage st (ldmatrix results are in registers)
        MBAR_ARRIVE(mb_empty + 8 * st);

        // refill stage (kc+3)
        const int ks = kc + 3;
        if (ks < NCH) {
            const int si = ks & 3;
            const int n  = ks >> 2;
            if (n >= 1) mbar_wait(mb_empty + 8 * si, (n - 1) & 1);
            issue(ks, si);
        }
    }

    // -------- fused LSTM epilogue (thread-local across gates) --------
    const int r  = lid >> 2;
    const int c0 = (lid & 3) * 2;
    const int hb = by * 4 + warpN;          // h-block of 8
    const int pb = d * 1536 + hb * 24;

#pragma unroll
    for (int mf = 0; mf < 4; mf++) {
#pragma unroll
        for (int rr = 0; rr < 2; rr++) {
            const int m = m0 + warpM * 64 + mf * 16 + rr * 8 + r;
#pragma unroll
            for (int cc = 0; cc < 2; cc++) {
                const int hi = c0 + cc;
                const int h  = hb * 8 + hi;
                const int q  = rr * 2 + cc;
                float iv = acc[mf][0][q] + __ldg(&Bp[pb + hi]);
                float gv = acc[mf][1][q] + __ldg(&Bp[pb + 8 + hi]);
                float ov = acc[mf][2][q] + __ldg(&Bp[pb + 16 + hi]);
                float cv = sig_(iv) * tanhf(gv);
                float hv = sig_(ov) * tanhf(cv);
                size_t o = (size_t)m * 1024 + d * HDIM + h;
                if (LAYER == 0) {
                    __nv_bfloat16 hh = __float2bfloat16_rn(hv);
                    g_A1h[o] = hh;
                    g_A1l[o] = __float2bfloat16_rn(hv - __bfloat162float(hh));
                } else {
                    g_h1[o] = hv;
                }
                if (d == 0 && (m & 255) == 255) {
                    hlast[(m >> 8) * HDIM + h] = hv;
                    clast[(m >> 8) * HDIM + h] = cv;
                }
            }
        }
    }
}

// ---------------- combine: enc[b,t,l,h] = h_l_fwd + h_l_bwd ----------------
__global__ void combine_kernel(float* __restrict__ enc)
{
    int idx = blockIdx.x * blockDim.x + threadIdx.x;
    const int total = MROWS * 128;    // 4 h-values per thread
    if (idx >= total) return;
    const int m  = idx >> 7;
    const int h4 = idx & 127;
    const size_t base = (size_t)m * 1024 + h4 * 4;

    float v0[4];
    {
        uint2 a = *reinterpret_cast<const uint2*>(g_A1h + base);
        uint2 b = *reinterpret_cast<const uint2*>(g_A1l + base);
        uint2 c = *reinterpret_cast<const uint2*>(g_A1h + base + 512);
        uint2 e = *reinterpret_cast<const uint2*>(g_A1l + base + 512);
        const __nv_bfloat16* ap = reinterpret_cast<const __nv_bfloat16*>(&a);
        const __nv_bfloat16* bp = reinterpret_cast<const __nv_bfloat16*>(&b);
        const __nv_bfloat16* cp = reinterpret_cast<const __nv_bfloat16*>(&c);
        const __nv_bfloat16* ep = reinterpret_cast<const __nv_bfloat16*>(&e);
#pragma unroll
        for (int q = 0; q < 4; q++)
            v0[q] = (__bfloat162float(ap[q]) + __bfloat162float(bp[q]))
                  + (__bfloat162float(cp[q]) + __bfloat162float(ep[q]));
    }
    float4 a1 = *reinterpret_cast<const float4*>(g_h1 + base);
    float4 b1 = *reinterpret_cast<const float4*>(g_h1 + base + 512);
    float4 v1 = make_float4(a1.x + b1.x, a1.y + b1.y, a1.z + b1.z, a1.w + b1.w);

    float4 v0f = make_float4(v0[0], v0[1], v0[2], v0[3]);
    *reinterpret_cast<float4*>(enc + ((size_t)m * 2 + 0) * HDIM + h4 * 4) = v0f;
    *reinterpret_cast<float4*>(enc + ((size_t)m * 2 + 1) * HDIM + h4 * 4) = v1;
}

extern "C" void kernel_launch(void* const* d_in, const int* in_sizes, int n_in,
                              void* d_out, int out_size)
{
    (void)in_sizes; (void)n_in; (void)out_size;
    const int*   x    = (const int*)d_in[0];
    const float* emb  = (const float*)d_in[1];
    const float* W0   = (const float*)d_in[2];
    const float* bih0 = (const float*)d_in[4];
    const float* bhh0 = (const float*)d_in[5];
    const float* W1   = (const float*)d_in[6];
    const float* bih1 = (const float*)d_in[8];
    const float* bhh1 = (const float*)d_in[9];

    float* out   = (float*)d_out;
    float* hlast = out;                      // (2,32,512)
    float* clast = out + 2 * 32 * HDIM;      // (2,32,512)
    float* enc   = out + 4 * 32 * HDIM;      // (32,256,2,512)

    cudaFuncSetAttribute(gemm_lstm<512, 0>,  cudaFuncAttributeMaxDynamicSharedMemorySize, SMEM_TOTAL);
    cudaFuncSetAttribute(gemm_lstm<1024, 1>, cudaFuncAttributeMaxDynamicSharedMemorySize, SMEM_TOTAL);

    gather_split<<<(MROWS * 128 + 255) / 256, 256>>>(x, emb);
    pack_w<512, 0><<<(2 * 1536 * 128 + 255) / 256, 256>>>(W0, bih0, bhh0);
    pack_w<1024, 1><<<(2 * 1536 * 256 + 255) / 256, 256>>>(W1, bih1, bhh1);

    dim3 grid(MROWS / BM, 1536 / BN, 2);
    gemm_lstm<512, 0><<<grid, NT, SMEM_TOTAL>>>(hlast, clast);
    gemm_lstm<1024, 1><<<grid, NT, SMEM_TOTAL>>>(hlast + 32 * HDIM, clast + 32 * HDIM);

    combine_kernel<<<(MROWS * 128 + 255) / 256, 256>>>(enc);
}

// round 15
// speedup vs baseline: 1.8025x; 1.4168x over previous
#include <cuda_runtime.h>
#include <cuda_fp16.h>
#include <cstdint>
#include <math.h>

// Problem: B=32,T=256 -> M=8192 rows; E=512, H=512; gates i,f,g,o (f unused since c0=0)
// Numeric scheme: fp16 2-chain. A quantized to fp16 (err ~2^-12, statistical over K),
// B split into fp16 hi+lo (residual ~2^-23). C = A*Bh + A*Bl, fp32 accumulate.
#define MROWS 8192
#define HDIM  512

// GEMM tiling (2 CTAs/SM, warp tile 64x24)
#define BM 128
#define BN 96            // 4 h-blocks of 8, each x3 gates (8-row interleave)
#define BK 32            // fp16 K per chunk (64 bytes per row)
#define NT 256           // 8 warps: 2 (M) x 4 (N)
#define NSTAGE 4
#define A_ST_BYTES 8192          // 128 rows * 64B (single fp16 array)
#define B_ST_BYTES 6144          // 96 rows * 64B, per hi/lo array
#define STAGE_BYTES (A_ST_BYTES + 2*B_ST_BYTES)     // 20480
#define MBAR_OFF    (NSTAGE * STAGE_BYTES)           // 81920
#define SMEM_TOTAL  (MBAR_OFF + 64)                  // 81984 -> 2 CTAs/SM easily

// ---------------- scratch (device globals; no allocs allowed) ----------------
__device__ __half g_A0[MROWS*512];
__device__ __half g_A1[MROWS*1024];                  // L0 output / L1 input (fp16)
__device__ __half g_W0h[2*1536*512],  g_W0l[2*1536*512];
__device__ __half g_W1h[2*1536*1024], g_W1l[2*1536*1024];
__device__ float g_Bp0[2*1536], g_Bp1[2*1536];
__device__ float g_h1[MROWS*1024];

// ---------------- PTX helpers (baseline ISA only) ----------------
__device__ __forceinline__ uint32_t smem_u32(const void* p) {
    uint32_t a;
    asm("{ .reg .u64 t; cvta.to.shared.u64 t, %1; cvt.u32.u64 %0, t; }" : "=r"(a) : "l"(p));
    return a;
}
#define CP_ASYNC16(dst, src) \
    asm volatile("cp.async.cg.shared.global [%0], [%1], 16;" :: "r"(dst), "l"(src))
#define CP_MBAR_ARRIVE(mb) \
    asm volatile("cp.async.mbarrier.arrive.noinc.shared.b64 [%0];" :: "r"(mb) : "memory")
#define MBAR_INIT(mb, c) \
    asm volatile("mbarrier.init.shared.b64 [%0], %1;" :: "r"(mb), "r"(c) : "memory")
#define MBAR_ARRIVE(mb) \
    asm volatile("{ .reg .b64 t; mbarrier.arrive.shared.b64 t, [%0]; }" :: "r"(mb) : "memory")

__device__ __forceinline__ void mbar_wait(uint32_t mb, uint32_t parity) {
    asm volatile(
        "{\n\t.reg .pred P;\n\t"
        "WL_%=:\n\t"
        "mbarrier.try_wait.parity.shared.b64 P, [%0], %1;\n\t"
        "@P bra.uni WD_%=;\n\t"
        "bra.uni WL_%=;\n\t"
        "WD_%=:\n\t}"
        :: "r"(mb), "r"(parity) : "memory");
}

#define LDSM_X4(r, addr) \
    asm volatile("ldmatrix.sync.aligned.m8n8.x4.shared.b16 {%0,%1,%2,%3}, [%4];" \
        : "=r"((r)[0]), "=r"((r)[1]), "=r"((r)[2]), "=r"((r)[3]) : "r"(addr))
#define LDSM_X2(r, addr) \
    asm volatile("ldmatrix.sync.aligned.m8n8.x2.shared.b16 {%0,%1}, [%2];" \
        : "=r"((r)[0]), "=r"((r)[1]) : "r"(addr))

#define MMA16816(d, a, b) \
    asm volatile("mma.sync.aligned.m16n8k16.row.col.f32.f16.f16.f32 " \
        "{%0,%1,%2,%3}, {%4,%5,%6,%7}, {%8,%9}, {%0,%1,%2,%3};" \
        : "+f"((d)[0]), "+f"((d)[1]), "+f"((d)[2]), "+f"((d)[3]) \
        : "r"((a)[0]), "r"((a)[1]), "r"((a)[2]), "r"((a)[3]), "r"((b)[0]), "r"((b)[1]))

__device__ __forceinline__ float sig_(float x) { return 1.0f / (1.0f + __expf(-x)); }

// 64B rows, 4x16B chunks; conflict-free swizzle for both cp.async and ldmatrix
__device__ __forceinline__ uint32_t swz64(int row, int chunk) {
    return (uint32_t)(row * 64 + ((chunk ^ ((row >> 1) & 3)) << 4));
}

// ---------------- prep kernels ----------------
__global__ void gather_q(const int* __restrict__ x, const float* __restrict__ emb)
{
    int id = blockIdx.x * blockDim.x + threadIdx.x;   // over MROWS*128 float4s
    if (id >= MROWS * 128) return;
    int m  = id >> 7;
    int c4 = id & 127;
    int tok = x[m];
    float4 v = *(reinterpret_cast<const float4*>(emb + (size_t)tok * 512) + c4);
    size_t o = (size_t)m * 512 + c4 * 4;
    __half2* dst = reinterpret_cast<__half2*>(g_A0 + o);
    dst[0] = __floats2half2_rn(v.x, v.y);
    dst[1] = __floats2half2_rn(v.z, v.w);
}

// packed row p = hb*24 + gate*8 + hi, h = hb*8 + hi, gates {i,g,o} <- src rows {0,2,3}
// W split into fp16 hi + lo; combined biases packed by p.
template <int K, int LAYER>
__global__ void pack_w(const float* __restrict__ W,
                       const float* __restrict__ bih, const float* __restrict__ bhh)
{
    __half* Wh = LAYER ? g_W1h : g_W0h;
    __half* Wl = LAYER ? g_W1l : g_W0l;
    float*  Bp = LAYER ? g_Bp1 : g_Bp0;

    const int KQ = K / 4;
    int id = blockIdx.x * blockDim.x + threadIdx.x;   // over 2*1536*KQ
    if (id >= 2 * 1536 * KQ) return;
    int dir = id / (1536 * KQ);
    int rem = id - dir * 1536 * KQ;
    int p   = rem / KQ;
    int c4  = rem - p * KQ;
    int hb   = p / 24;
    int w    = p - hb * 24;
    int gate = w >> 3;
    int hi   = w & 7;
    int h    = hb * 8 + hi;
    int gsrc = (gate == 0) ? 0 : (gate + 1);   // i->0, g->2, o->3
    size_t src = ((size_t)dir * 2048 + gsrc * 512 + h) * K + c4 * 4;
    size_t dst = ((size_t)dir * 1536 + p) * K + c4 * 4;
    float4 v = *reinterpret_cast<const float4*>(W + src);
    float vv[4] = {v.x, v.y, v.z, v.w};
#pragma unroll
    for (int q = 0; q < 4; q++) {
        __half h16 = __float2half_rn(vv[q]);
        Wh[dst + q] = h16;
        Wl[dst + q] = __float2half_rn(vv[q] - __half2float(h16));
    }
    if (c4 == 0) {
        int bi = dir * 2048 + gsrc * 512 + h;
        Bp[dir * 1536 + p] = bih[bi] + bhh[bi];
    }
}

// ---------------- fused fp16 2-chain GEMM (mma.sync, mbarrier pipeline) ----------------
template <int K, int LAYER>
__global__ __launch_bounds__(NT, 2) void gemm_lstm(float* __restrict__ hlast,
                                                   float* __restrict__ clast)
{
    extern __shared__ char smem[];
    const uint32_t sb = smem_u32(smem);
    const uint32_t mb_full  = sb + MBAR_OFF;        // 4 x 8B
    const uint32_t mb_empty = sb + MBAR_OFF + 32;   // 4 x 8B

    const int tid = threadIdx.x;
    const int wid = tid >> 5;
    const int lid = tid & 31;
    const int warpM = wid >> 2;          // 0..1
    const int warpN = wid & 3;           // 0..3

    const int m0 = blockIdx.x * BM;
    const int by = blockIdx.y;           // 16 n-tiles of 96 packed rows
    const int d  = blockIdx.z;

    const __half* A  = LAYER ? g_A1 : g_A0;
    const __half* Wh = LAYER ? g_W1h : g_W0h;
    const __half* Wl = LAYER ? g_W1l : g_W0l;
    const float*  Bp = LAYER ? g_Bp1 : g_Bp0;
    const int nrow0 = d * 1536 + by * BN;

    constexpr int NCH = K / BK;

    if (tid == 0) {
#pragma unroll
        for (int s = 0; s < NSTAGE; s++) {
            MBAR_INIT(mb_full  + 8 * s, NT);
            MBAR_INIT(mb_empty + 8 * s, NT);
        }
    }
    __syncthreads();

    // ---- hoisted per-thread loader state ----
    const int arow = tid >> 2;
    const int ach  = tid & 3;
    const __half* aSrc = A + (size_t)(m0 + arow) * K + ach * 8;
    const uint32_t aDst = swz64(arow, ach);          // +4096 for row+64
    const __half* bSrc[3];
    uint32_t bDst[3];
#pragma unroll
    for (int it = 0; it < 3; it++) {
        int idx = tid + it * NT;
        int arr = (idx >= 384) ? 1 : 0;
        int rem = idx - arr * 384;
        int row = rem >> 2;
        int c   = rem & 3;
        bSrc[it] = (arr ? Wl : Wh) + (size_t)(nrow0 + row) * K + c * 8;
        bDst[it] = A_ST_BYTES + arr * B_ST_BYTES + swz64(row, c);
    }

    auto issue = [&](int kc, int stage) {
        const uint32_t so = sb + stage * STAGE_BYTES;
        const int ko = kc * BK;
        CP_ASYNC16(so + aDst,        aSrc + ko);
        CP_ASYNC16(so + aDst + 4096, aSrc + ko + (size_t)64 * K);
#pragma unroll
        for (int it = 0; it < 3; it++)
            CP_ASYNC16(so + bDst[it], bSrc[it] + ko);
        CP_MBAR_ARRIVE(mb_full + 8 * stage);
    };

    float acc[4][3][4];
#pragma unroll
    for (int mf = 0; mf < 4; mf++)
#pragma unroll
        for (int g = 0; g < 3; g++)
#pragma unroll
            for (int q = 0; q < 4; q++) acc[mf][g][q] = 0.0f;

    // prologue fills (stages 0..2)
    issue(0, 0);
    issue(1, 1);
    issue(2, 2);

    // ---- precomputed per-kg LDSM offsets (within a stage) ----
    const int la_row = (lid & 7) + ((lid >> 3) & 1) * 8;
    const int la_ch  = (lid >> 4);
    const int lb_row = (lid & 7) + ((lid >> 4) << 3);
    const int lb_ch  = ((lid >> 3) & 1);
    const int lo_row = 16 + (lid & 7);
    uint32_t aoff[2][4], b4off[2], b2off[2];
#pragma unroll
    for (int kg = 0; kg < 2; kg++) {
#pragma unroll
        for (int mf = 0; mf < 4; mf++)
            aoff[kg][mf] = swz64(warpM * 64 + mf * 16 + la_row, kg * 2 + la_ch);
        b4off[kg] = A_ST_BYTES + swz64(warpN * 24 + lb_row, kg * 2 + lb_ch);
        b2off[kg] = A_ST_BYTES + swz64(warpN * 24 + lo_row, kg * 2 + lb_ch);
    }

    for (int kc = 0; kc < NCH; kc++) {
        const int st = kc & 3;
        mbar_wait(mb_full + 8 * st, (kc >> 2) & 1);

        const uint32_t sS = sb + st * STAGE_BYTES;

#pragma unroll
        for (int kg = 0; kg < 2; kg++) {
            uint32_t aF[4][4], bH[3][2], bL[3][2];
#pragma unroll
            for (int mf = 0; mf < 4; mf++)
                LDSM_X4(aF[mf], sS + aoff[kg][mf]);
            {
                uint32_t t[4];
                LDSM_X4(t, sS + b4off[kg]);
                bH[0][0] = t[0]; bH[0][1] = t[1]; bH[1][0] = t[2]; bH[1][1] = t[3];
                LDSM_X4(t, sS + b4off[kg] + B_ST_BYTES);
                bL[0][0] = t[0]; bL[0][1] = t[1]; bL[1][0] = t[2]; bL[1][1] = t[3];
                LDSM_X2(bH[2], sS + b2off[kg]);
                LDSM_X2(bL[2], sS + b2off[kg] + B_ST_BYTES);
            }
#pragma unroll
            for (int mf = 0; mf < 4; mf++)
#pragma unroll
                for (int g = 0; g < 3; g++) MMA16816(acc[mf][g], aF[mf], bH[g]);
#pragma unroll
            for (int mf = 0; mf < 4; mf++)
#pragma unroll
                for (int g = 0; g < 3; g++) MMA16816(acc[mf][g], aF[mf], bL[g]);
        }

        MBAR_ARRIVE(mb_empty + 8 * st);

        const int ks = kc + 3;
        if (ks < NCH) {
            const int si = ks & 3;
            const int n  = ks >> 2;
            if (n >= 1) mbar_wait(mb_empty + 8 * si, (n - 1) & 1);
            issue(ks, si);
        }
    }

    // -------- fused LSTM epilogue (thread-local across gates) --------
    const int r  = lid >> 2;
    const int c0 = (lid & 3) * 2;
    const int hb = by * 4 + warpN;          // h-block of 8
    const int pb = d * 1536 + hb * 24;

#pragma unroll
    for (int mf = 0; mf < 4; mf++) {
#pragma unroll
        for (int rr = 0; rr < 2; rr++) {
            const int m = m0 + warpM * 64 + mf * 16 + rr * 8 + r;
#pragma unroll
            for (int cc = 0; cc < 2; cc++) {
                const int hi = c0 + cc;
                const int h  = hb * 8 + hi;
                const int q  = rr * 2 + cc;
                float iv = acc[mf][0][q] + __ldg(&Bp[pb + hi]);
                float gv = acc[mf][1][q] + __ldg(&Bp[pb + 8 + hi]);
                float ov = acc[mf][2][q] + __ldg(&Bp[pb + 16 + hi]);
                float cv = sig_(iv) * tanhf(gv);
                float hv = sig_(ov) * tanhf(cv);
                size_t o = (size_t)m * 1024 + d * HDIM + h;
                if (LAYER == 0) {
                    g_A1[o] = __float2half_rn(hv);   // L1 input + combine source
                } else {
                    g_h1[o] = hv;
                }
                if (d == 0 && (m & 255) == 255) {
                    hlast[(m >> 8) * HDIM + h] = hv;
                    clast[(m >> 8) * HDIM + h] = cv;
                }
            }
        }
    }
}

// ---------------- combine: enc[b,t,l,h] = h_l_fwd + h_l_bwd ----------------
// l=0 from fp16 store (err <= 2^-12 |h|); l=1 from fp32.
__global__ void combine_kernel(float* __restrict__ enc)
{
    int idx = blockIdx.x * blockDim.x + threadIdx.x;
    const int total = MROWS * 128;    // 4 h-values per thread
    if (idx >= total) return;
    const int m  = idx >> 7;
    const int h4 = idx & 127;
    const size_t base = (size_t)m * 1024 + h4 * 4;

    const __half2* f0 = reinterpret_cast<const __half2*>(g_A1 + base);
    const __half2* b0 = reinterpret_cast<const __half2*>(g_A1 + base + 512);
    float2 fa = __half22float2(f0[0]), fb = __half22float2(f0[1]);
    float2 ba = __half22float2(b0[0]), bb = __half22float2(b0[1]);
    float4 v0 = make_float4(fa.x + ba.x, fa.y + ba.y, fb.x + bb.x, fb.y + bb.y);

    float4 a1 = *reinterpret_cast<const float4*>(g_h1 + base);
    float4 b1 = *reinterpret_cast<const float4*>(g_h1 + base + 512);
    float4 v1 = make_float4(a1.x + b1.x, a1.y + b1.y, a1.z + b1.z, a1.w + b1.w);

    *reinterpret_cast<float4*>(enc + ((size_t)m * 2 + 0) * HDIM + h4 * 4) = v0;
    *reinterpret_cast<float4*>(enc + ((size_t)m * 2 + 1) * HDIM + h4 * 4) = v1;
}

extern "C" void kernel_launch(void* const* d_in, const int* in_sizes, int n_in,
                              void* d_out, int out_size)
{
    (void)in_sizes; (void)n_in; (void)out_size;
    const int*   x    = (const int*)d_in[0];
    const float* emb  = (const float*)d_in[1];
    const float* W0   = (const float*)d_in[2];
    const float* bih0 = (const float*)d_in[4];
    const float* bhh0 = (const float*)d_in[5];
    const float* W1   = (const float*)d_in[6];
    const float* bih1 = (const float*)d_in[8];
    const float* bhh1 = (const float*)d_in[9];

    float* out   = (float*)d_out;
    float* hlast = out;                      // (2,32,512)
    float* clast = out + 2 * 32 * HDIM;      // (2,32,512)
    float* enc   = out + 4 * 32 * HDIM;      // (32,256,2,512)

    cudaFuncSetAttribute(gemm_lstm<512, 0>,  cudaFuncAttributeMaxDynamicSharedMemorySize, SMEM_TOTAL);
    cudaFuncSetAttribute(gemm_lstm<1024, 1>, cudaFuncAttributeMaxDynamicSharedMemorySize, SMEM_TOTAL);

    gather_q<<<(MROWS * 128 + 255) / 256, 256>>>(x, emb);
    pack_w<512, 0><<<(2 * 1536 * 128 + 255) / 256, 256>>>(W0, bih0, bhh0);
    pack_w<1024, 1><<<(2 * 1536 * 256 + 255) / 256, 256>>>(W1, bih1, bhh1);

    dim3 grid(MROWS / BM, 1536 / BN, 2);
    gemm_lstm<512, 0><<<grid, NT, SMEM_TOTAL>>>(hlast, clast);
    gemm_lstm<1024, 1><<<grid, NT, SMEM_TOTAL>>>(hlast + 32 * HDIM, clast + 32 * HDIM);

    combine_kernel<<<(MROWS * 128 + 255) / 256, 256>>>(enc);
}